// round 7
// baseline (speedup 1.0000x reference)
#include <cuda_runtime.h>
#include <math.h>

// Problem constants
#define E_DIM 1024
#define NHEAD 16
#define HDIM  64
#define BATCH 4
#define SQL   2048
#define SKL   2048

// Scratch (allocation-free rule: __device__ globals)
__device__ float g_Q [BATCH * SQL * E_DIM];
__device__ float g_K [BATCH * SKL * E_DIM];
__device__ float g_V [BATCH * SKL * E_DIM];
__device__ float g_AO[BATCH * SQL * E_DIM];
__device__ float g_attn_fb[268435456];   // fallback if out only covers `output`

// ---------------------------------------------------------------------------
// TF32 split helpers: x = hi + lo (hi = RN-rounded tf32, lo = residual)
// ---------------------------------------------------------------------------
__device__ __forceinline__ void tf32_split(float x, float& hi, float& lo)
{
    unsigned hb;
    asm("cvt.rna.tf32.f32 %0, %1;" : "=r"(hb) : "f"(x));
    float h = __uint_as_float(hb);
    float l = x - h;
    unsigned lb;
    asm("cvt.rna.tf32.f32 %0, %1;" : "=r"(lb) : "f"(l));
    hi = h;
    lo = __uint_as_float(lb);
}

__device__ __forceinline__ void mma_tf32(float* d, const unsigned* a, const unsigned* b)
{
    asm volatile(
        "mma.sync.aligned.m16n8k8.row.col.f32.tf32.tf32.f32 "
        "{%0,%1,%2,%3}, {%4,%5,%6,%7}, {%8,%9}, {%0,%1,%2,%3};"
        : "+f"(d[0]), "+f"(d[1]), "+f"(d[2]), "+f"(d[3])
        : "r"(a[0]), "r"(a[1]), "r"(a[2]), "r"(a[3]), "r"(b[0]), "r"(b[1]));
}

// ---------------------------------------------------------------------------
// Tensor-core batched GEMM with tf32 2-term split (fp32-grade accuracy).
//   NT:  C = alpha*(A @ B^T) + bias   A:[M,K] lda, B:[N,K] ldb
//   NN:  C = alpha*(A @ B)   + bias   A:[M,K] lda, B:[K,N] ldb
// Block tile BMxBN, K-tile BK=32. WR x WC warps (8 total, 256 threads).
// All dims assumed multiples of tile sizes (true for every shape here).
// ---------------------------------------------------------------------------
template<int BM, int BN, int BK, int WR, int WC, bool NT>
__global__ void mma_gemm(
    const float* __restrict__ A, int lda, long sAb, long sAh,
    const float* __restrict__ B, int ldb, long sBb, long sBh,
    float* __restrict__ C, int ldc, long sCb, long sCh,
    const float* __restrict__ bias, int K, float alpha, int hPer)
{
    constexpr int WM = BM / WR, WN = BN / WC;
    constexpr int MT_M = WM / 16, MT_N = WN / 8;
    constexpr int PA = BK + 4;
    constexpr int PB = NT ? (BK + 4) : (BK + 1);
    constexpr int NTHREADS = WR * WC * 32;

    int bz = blockIdx.z;
    int b = bz / hPer, h = bz - b * hPer;
    A += (long)b * sAb + (long)h * sAh;
    B += (long)b * sBb + (long)h * sBh;
    C += (long)b * sCb + (long)h * sCh;

    extern __shared__ float sm[];
    float* AsHi = sm;
    float* AsLo = AsHi + BM * PA;
    float* BsHi = AsLo + BM * PA;
    float* BsLo = BsHi + BN * PB;

    const int tid  = threadIdx.x;
    const int warp = tid >> 5, lane = tid & 31;
    const int lr = lane >> 2, lc = lane & 3;
    const int wm = (warp / WC) * WM;
    const int wn = (warp % WC) * WN;
    const int row0 = blockIdx.y * BM, col0 = blockIdx.x * BN;

    float acc[MT_M][MT_N][4];
#pragma unroll
    for (int i = 0; i < MT_M; i++)
#pragma unroll
        for (int j = 0; j < MT_N; j++)
#pragma unroll
            for (int q = 0; q < 4; q++) acc[i][j][q] = 0.0f;

    for (int k0 = 0; k0 < K; k0 += BK) {
        // ---- stage A tile [BM x BK] (always row-major, k-contiguous) ----
#pragma unroll
        for (int i = tid; i < BM * BK / 4; i += NTHREADS) {
            int r = i / (BK / 4), cq = i % (BK / 4);
            float4 v = *(const float4*)&A[(long)(row0 + r) * lda + k0 + cq * 4];
            float4 h4, l4;
            tf32_split(v.x, h4.x, l4.x); tf32_split(v.y, h4.y, l4.y);
            tf32_split(v.z, h4.z, l4.z); tf32_split(v.w, h4.w, l4.w);
            *(float4*)&AsHi[r * PA + cq * 4] = h4;
            *(float4*)&AsLo[r * PA + cq * 4] = l4;
        }
        // ---- stage B tile into [BN][BK] (k-contiguous in smem) ----
        if (NT) {
#pragma unroll
            for (int i = tid; i < BN * BK / 4; i += NTHREADS) {
                int r = i / (BK / 4), cq = i % (BK / 4);
                float4 v = *(const float4*)&B[(long)(col0 + r) * ldb + k0 + cq * 4];
                float4 h4, l4;
                tf32_split(v.x, h4.x, l4.x); tf32_split(v.y, h4.y, l4.y);
                tf32_split(v.z, h4.z, l4.z); tf32_split(v.w, h4.w, l4.w);
                *(float4*)&BsHi[r * PB + cq * 4] = h4;
                *(float4*)&BsLo[r * PB + cq * 4] = l4;
            }
        } else {
#pragma unroll
            for (int i = tid; i < BK * BN / 4; i += NTHREADS) {
                int kr = i / (BN / 4), nq = i % (BN / 4);
                float4 v = *(const float4*)&B[(long)(k0 + kr) * ldb + col0 + nq * 4];
                float hh, ll;
                tf32_split(v.x, hh, ll); BsHi[(nq*4+0) * PB + kr] = hh; BsLo[(nq*4+0) * PB + kr] = ll;
                tf32_split(v.y, hh, ll); BsHi[(nq*4+1) * PB + kr] = hh; BsLo[(nq*4+1) * PB + kr] = ll;
                tf32_split(v.z, hh, ll); BsHi[(nq*4+2) * PB + kr] = hh; BsLo[(nq*4+2) * PB + kr] = ll;
                tf32_split(v.w, hh, ll); BsHi[(nq*4+3) * PB + kr] = hh; BsLo[(nq*4+3) * PB + kr] = ll;
            }
        }
        __syncthreads();

        // ---- compute: BK/8 mma k-steps ----
#pragma unroll
        for (int kk = 0; kk < BK; kk += 8) {
            unsigned bh[MT_N][2], bl[MT_N][2];
#pragma unroll
            for (int in = 0; in < MT_N; in++) {
                int n = wn + in * 8 + lr;
                bh[in][0] = __float_as_uint(BsHi[n * PB + kk + lc]);
                bh[in][1] = __float_as_uint(BsHi[n * PB + kk + lc + 4]);
                bl[in][0] = __float_as_uint(BsLo[n * PB + kk + lc]);
                bl[in][1] = __float_as_uint(BsLo[n * PB + kk + lc + 4]);
            }
#pragma unroll
            for (int im = 0; im < MT_M; im++) {
                int r = wm + im * 16 + lr;
                unsigned ah[4], al[4];
                ah[0] = __float_as_uint(AsHi[r * PA + kk + lc]);
                ah[1] = __float_as_uint(AsHi[(r + 8) * PA + kk + lc]);
                ah[2] = __float_as_uint(AsHi[r * PA + kk + lc + 4]);
                ah[3] = __float_as_uint(AsHi[(r + 8) * PA + kk + lc + 4]);
                al[0] = __float_as_uint(AsLo[r * PA + kk + lc]);
                al[1] = __float_as_uint(AsLo[(r + 8) * PA + kk + lc]);
                al[2] = __float_as_uint(AsLo[r * PA + kk + lc + 4]);
                al[3] = __float_as_uint(AsLo[(r + 8) * PA + kk + lc + 4]);
#pragma unroll
                for (int in = 0; in < MT_N; in++) {
                    mma_tf32(acc[im][in], ah, bh[in]);   // hi*hi
                    mma_tf32(acc[im][in], ah, bl[in]);   // hi*lo
                    mma_tf32(acc[im][in], al, bh[in]);   // lo*hi
                }
            }
        }
        __syncthreads();
    }

    // ---- epilogue ----
#pragma unroll
    for (int im = 0; im < MT_M; im++) {
#pragma unroll
        for (int in = 0; in < MT_N; in++) {
            int r = row0 + wm + im * 16 + lr;
            int c = col0 + wn + in * 8 + lc * 2;
            float b0 = bias ? bias[c]     : 0.0f;
            float b1 = bias ? bias[c + 1] : 0.0f;
            float2 v0 = { acc[im][in][0] * alpha + b0, acc[im][in][1] * alpha + b1 };
            float2 v1 = { acc[im][in][2] * alpha + b0, acc[im][in][3] * alpha + b1 };
            *(float2*)&C[(long)r * ldc + c]       = v0;
            *(float2*)&C[(long)(r + 8) * ldc + c] = v1;
        }
    }
}

// ---------------------------------------------------------------------------
// Row softmax, in place. One block of 256 threads per row of 2048 floats.
// ---------------------------------------------------------------------------
__global__ void softmax_kernel(float* __restrict__ attn)
{
    long row = blockIdx.x;
    float* p = attn + row * (long)SKL;
    int t = threadIdx.x;

    float4* p4 = (float4*)p;
    float4 v0 = p4[t];
    float4 v1 = p4[t + 256];

    __shared__ float sh[8];

    float m = fmaxf(fmaxf(fmaxf(v0.x, v0.y), fmaxf(v0.z, v0.w)),
                    fmaxf(fmaxf(v1.x, v1.y), fmaxf(v1.z, v1.w)));
#pragma unroll
    for (int o = 16; o > 0; o >>= 1)
        m = fmaxf(m, __shfl_xor_sync(0xffffffffu, m, o));
    if ((t & 31) == 0) sh[t >> 5] = m;
    __syncthreads();
    {
        float mm = sh[0];
#pragma unroll
        for (int w = 1; w < 8; w++) mm = fmaxf(mm, sh[w]);
        m = mm;
    }
    __syncthreads();

    v0.x = __expf(v0.x - m); v0.y = __expf(v0.y - m);
    v0.z = __expf(v0.z - m); v0.w = __expf(v0.w - m);
    v1.x = __expf(v1.x - m); v1.y = __expf(v1.y - m);
    v1.z = __expf(v1.z - m); v1.w = __expf(v1.w - m);

    float s = v0.x + v0.y + v0.z + v0.w + v1.x + v1.y + v1.z + v1.w;
#pragma unroll
    for (int o = 16; o > 0; o >>= 1)
        s += __shfl_xor_sync(0xffffffffu, s, o);
    if ((t & 31) == 0) sh[t >> 5] = s;
    __syncthreads();
    {
        float ss = sh[0];
#pragma unroll
        for (int w = 1; w < 8; w++) ss += sh[w];
        s = ss;
    }

    float r = 1.0f / s;
    v0.x *= r; v0.y *= r; v0.z *= r; v0.w *= r;
    v1.x *= r; v1.y *= r; v1.z *= r; v1.w *= r;

    p4[t]       = v0;
    p4[t + 256] = v1;
}

// ---------------------------------------------------------------------------
extern "C" void kernel_launch(void* const* d_in, const int* in_sizes, int n_in,
                              void* d_out, int out_size)
{
    const float* query = (const float*)d_in[0];
    const float* key   = (const float*)d_in[1];
    const float* value = (const float*)d_in[2];
    const float* Wq    = (const float*)d_in[3];
    const float* bq    = (const float*)d_in[4];
    const float* Wk    = (const float*)d_in[5];
    const float* bk    = (const float*)d_in[6];
    const float* Wv    = (const float*)d_in[7];
    const float* bv    = (const float*)d_in[8];
    const float* Wo    = (const float*)d_in[9];
    const float* bo    = (const float*)d_in[10];
    float* out = (float*)d_out;

    float *Qp, *Kp, *Vp, *AOp, *attn_fb;
    cudaGetSymbolAddress((void**)&Qp,  g_Q);
    cudaGetSymbolAddress((void**)&Kp,  g_K);
    cudaGetSymbolAddress((void**)&Vp,  g_V);
    cudaGetSymbolAddress((void**)&AOp, g_AO);
    cudaGetSymbolAddress((void**)&attn_fb, g_attn_fb);

    const long OUT_ELEMS  = (long)BATCH * SQL * E_DIM;
    const long ATTN_ELEMS = (long)BATCH * NHEAD * SQL * (long)SKL;
    float* attn = ((long)out_size >= OUT_ELEMS + ATTN_ELEMS) ? (out + OUT_ELEMS)
                                                             : attn_fb;

    // Kernel instantiations
    auto knt = mma_gemm<128, 128, 32, 2, 4, true>;   // NT, 128x128 tiles
    auto knn = mma_gemm<128,  64, 32, 4, 2, false>;  // NN, 128x64 tiles (PV)

    const int SM_NT = (2 * 128 * 36 + 2 * 128 * 36) * 4;   // 73728 B
    const int SM_NN = (2 * 128 * 36 + 2 *  64 * 33) * 4;   // 53760 B
    cudaFuncSetAttribute(knt, cudaFuncAttributeMaxDynamicSharedMemorySize, SM_NT);
    cudaFuncSetAttribute(knn, cudaFuncAttributeMaxDynamicSharedMemorySize, SM_NN);

    dim3 blk(256);

    // 1) QKV projections: [8192,1024] @ W^T + b
    {
        dim3 g(E_DIM / 128, (BATCH * SQL) / 128, 1);
        knt<<<g, blk, SM_NT>>>(query, E_DIM, 0, 0, Wq, E_DIM, 0, 0,
                               Qp, E_DIM, 0, 0, bq, E_DIM, 1.0f, 1);
        knt<<<g, blk, SM_NT>>>(key,   E_DIM, 0, 0, Wk, E_DIM, 0, 0,
                               Kp, E_DIM, 0, 0, bk, E_DIM, 1.0f, 1);
        knt<<<g, blk, SM_NT>>>(value, E_DIM, 0, 0, Wv, E_DIM, 0, 0,
                               Vp, E_DIM, 0, 0, bv, E_DIM, 1.0f, 1);
    }

    // 2) scores = (Q_h @ K_h^T) / 8 per (b,h)
    {
        dim3 g(SKL / 128, SQL / 128, BATCH * NHEAD);
        knt<<<g, blk, SM_NT>>>(
            Qp, E_DIM, (long)SQL * E_DIM, (long)HDIM,
            Kp, E_DIM, (long)SKL * E_DIM, (long)HDIM,
            attn, SKL, (long)NHEAD * SQL * SKL, (long)SQL * SKL,
            nullptr, HDIM, 0.125f, NHEAD);
    }

    // 3) softmax rows, in place
    softmax_kernel<<<BATCH * NHEAD * SQL, 256>>>(attn);

    // 4) attn_out_h = attn @ V_h per (b,h)
    {
        dim3 g(HDIM / 64, SQL / 128, BATCH * NHEAD);
        knn<<<g, blk, SM_NN>>>(
            attn, SKL, (long)NHEAD * SQL * SKL, (long)SQL * SKL,
            Vp, E_DIM, (long)SKL * E_DIM, (long)HDIM,
            AOp, E_DIM, (long)SQL * E_DIM, (long)HDIM,
            nullptr, SKL, 1.0f, NHEAD);
    }

    // 5) output = attn_out @ Wo^T + bo
    {
        dim3 g(E_DIM / 128, (BATCH * SQL) / 128, 1);
        knt<<<g, blk, SM_NT>>>(AOp, E_DIM, 0, 0, Wo, E_DIM, 0, 0,
                               out, E_DIM, 0, 0, bo, E_DIM, 1.0f, 1);
    }
}

// round 10
// speedup vs baseline: 1.1898x; 1.1898x over previous
#include <cuda_runtime.h>
#include <math.h>

// Problem constants
#define E_DIM 1024
#define NHEAD 16
#define HDIM  64
#define BATCH 4
#define SQL   2048
#define SKL   2048

// Scratch (allocation-free rule: __device__ globals)
__device__ float g_Q [BATCH * SQL * E_DIM];
__device__ float g_K [BATCH * SKL * E_DIM];
__device__ float g_V [BATCH * SKL * E_DIM];
__device__ float g_AO[BATCH * SQL * E_DIM];
__device__ float g_attn_fb[268435456];   // fallback if out only covers `output`

// ---------------------------------------------------------------------------
// TF32 split: x = hi + lo (hi = RNA-rounded tf32, lo = tf32(residual))
// ---------------------------------------------------------------------------
__device__ __forceinline__ void tf32_split_u(float x, unsigned& hi, unsigned& lo)
{
    unsigned hb;
    asm("cvt.rna.tf32.f32 %0, %1;" : "=r"(hb) : "f"(x));
    float l = x - __uint_as_float(hb);
    unsigned lb;
    asm("cvt.rna.tf32.f32 %0, %1;" : "=r"(lb) : "f"(l));
    hi = hb; lo = lb;
}

__device__ __forceinline__ void mma_tf32(float* d, const unsigned* a, const unsigned* b)
{
    asm volatile(
        "mma.sync.aligned.m16n8k8.row.col.f32.tf32.tf32.f32 "
        "{%0,%1,%2,%3}, {%4,%5,%6,%7}, {%8,%9}, {%0,%1,%2,%3};"
        : "+f"(d[0]), "+f"(d[1]), "+f"(d[2]), "+f"(d[3])
        : "r"(a[0]), "r"(a[1]), "r"(a[2]), "r"(a[3]), "r"(b[0]), "r"(b[1]));
}

// cp.async helpers
__device__ __forceinline__ void cp_async16(void* dst, const void* src)
{
    unsigned d = (unsigned)__cvta_generic_to_shared(dst);
    asm volatile("cp.async.cg.shared.global [%0], [%1], 16;\n" :: "r"(d), "l"(src));
}
__device__ __forceinline__ void cp_async4(void* dst, const void* src)
{
    unsigned d = (unsigned)__cvta_generic_to_shared(dst);
    asm volatile("cp.async.ca.shared.global [%0], [%1], 4;\n" :: "r"(d), "l"(src));
}
__device__ __forceinline__ void cp_commit() { asm volatile("cp.async.commit_group;\n" ::: "memory"); }
__device__ __forceinline__ void cp_wait1()  { asm volatile("cp.async.wait_group 1;\n" ::: "memory"); }

// ---------------------------------------------------------------------------
// Tensor-core batched GEMM, tf32 2-term split, cp.async double-buffered.
//   NT:  C = alpha*(A @ B^T) + bias   A:[M,K] lda, B:[N,K] ldb
//   NN:  C = alpha*(A @ B)   + bias   A:[M,K] lda, B:[K,N] ldb
// Raw fp32 staged in smem; hi/lo split happens at fragment-load time.
// ---------------------------------------------------------------------------
template<int BM, int BN, int BK, int WR, int WC, bool NT>
__global__ void __launch_bounds__(256, 2) mma_gemm(
    const float* __restrict__ A, int lda, long sAb, long sAh,
    const float* __restrict__ B, int ldb, long sBb, long sBh,
    float* __restrict__ C, int ldc, long sCb, long sCh,
    const float* __restrict__ bias, int K, float alpha, int hPer)
{
    constexpr int WM = BM / WR, WN = BN / WC;
    constexpr int MT_M = WM / 16, MT_N = WN / 8;
    constexpr int PA = BK + 4;                 // 16B-aligned rows (36 floats = 144B)
    constexpr int PB = NT ? (BK + 4) : (BK + 1);
    constexpr int NTHREADS = WR * WC * 32;
    constexpr int ASZ = BM * PA, BSZ = BN * PB;

    int bz = blockIdx.z;
    int b = bz / hPer, h = bz - b * hPer;
    A += (long)b * sAb + (long)h * sAh;
    B += (long)b * sBb + (long)h * sBh;
    C += (long)b * sCb + (long)h * sCh;

    extern __shared__ float sm[];   // [2][ASZ] A stages, then [2][BSZ] B stages
    float* As[2] = { sm, sm + ASZ };
    float* Bs[2] = { sm + 2 * ASZ, sm + 2 * ASZ + BSZ };

    const int tid  = threadIdx.x;
    const int warp = tid >> 5, lane = tid & 31;
    const int lr = lane >> 2, lc = lane & 3;
    const int wm = (warp / WC) * WM;
    const int wn = (warp % WC) * WN;
    const int row0 = blockIdx.y * BM, col0 = blockIdx.x * BN;

    float acc[MT_M][MT_N][4];
#pragma unroll
    for (int i = 0; i < MT_M; i++)
#pragma unroll
        for (int j = 0; j < MT_N; j++)
#pragma unroll
            for (int q = 0; q < 4; q++) acc[i][j][q] = 0.0f;

    const int nt = K / BK;

    // ---- tile staging (cp.async) ----
    auto stage = [&](int k0, int buf) {
        float* Ad = As[buf];
        float* Bd = Bs[buf];
        // A tile [BM x BK], k-contiguous, float4 chunks
#pragma unroll
        for (int i = tid; i < BM * (BK / 4); i += NTHREADS) {
            int r = i / (BK / 4), cq = i % (BK / 4);
            cp_async16(&Ad[r * PA + cq * 4], &A[(long)(row0 + r) * lda + k0 + cq * 4]);
        }
        if (NT) {
#pragma unroll
            for (int i = tid; i < BN * (BK / 4); i += NTHREADS) {
                int r = i / (BK / 4), cq = i % (BK / 4);
                cp_async16(&Bd[r * PB + cq * 4], &B[(long)(col0 + r) * ldb + k0 + cq * 4]);
            }
        } else {
            // B [K,N] -> smem [BN][PB] transposed, 4B cp.async, conflict-free (PB odd)
#pragma unroll
            for (int i = tid; i < BK * BN; i += NTHREADS) {
                int kr = i / BN, n = i % BN;
                cp_async4(&Bd[n * PB + kr], &B[(long)(k0 + kr) * ldb + col0 + n]);
            }
        }
    };

    stage(0, 0);
    cp_commit();

    for (int t = 0; t < nt; t++) {
        if (t + 1 < nt) stage((t + 1) * BK, (t + 1) & 1);
        cp_commit();
        cp_wait1();
        __syncthreads();

        const float* Ab = As[t & 1];
        const float* Bb = Bs[t & 1];

#pragma unroll
        for (int kk = 0; kk < BK; kk += 8) {
            unsigned bh[MT_N][2], bl[MT_N][2];
#pragma unroll
            for (int in = 0; in < MT_N; in++) {
                int n = wn + in * 8 + lr;
                tf32_split_u(Bb[n * PB + kk + lc],     bh[in][0], bl[in][0]);
                tf32_split_u(Bb[n * PB + kk + lc + 4], bh[in][1], bl[in][1]);
            }
#pragma unroll
            for (int im = 0; im < MT_M; im++) {
                int r = wm + im * 16 + lr;
                unsigned ah[4], al[4];
                tf32_split_u(Ab[r * PA + kk + lc],           ah[0], al[0]);
                tf32_split_u(Ab[(r + 8) * PA + kk + lc],     ah[1], al[1]);
                tf32_split_u(Ab[r * PA + kk + lc + 4],       ah[2], al[2]);
                tf32_split_u(Ab[(r + 8) * PA + kk + lc + 4], ah[3], al[3]);
#pragma unroll
                for (int in = 0; in < MT_N; in++) {
                    mma_tf32(acc[im][in], ah, bh[in]);   // hi*hi
                    mma_tf32(acc[im][in], ah, bl[in]);   // hi*lo
                    mma_tf32(acc[im][in], al, bh[in]);   // lo*hi
                }
            }
        }
        __syncthreads();
    }

    // ---- epilogue ----
#pragma unroll
    for (int im = 0; im < MT_M; im++) {
#pragma unroll
        for (int in = 0; in < MT_N; in++) {
            int r = row0 + wm + im * 16 + lr;
            int c = col0 + wn + in * 8 + lc * 2;
            float b0 = bias ? bias[c]     : 0.0f;
            float b1 = bias ? bias[c + 1] : 0.0f;
            float2 v0 = { acc[im][in][0] * alpha + b0, acc[im][in][1] * alpha + b1 };
            float2 v1 = { acc[im][in][2] * alpha + b0, acc[im][in][3] * alpha + b1 };
            *(float2*)&C[(long)r * ldc + c]       = v0;
            *(float2*)&C[(long)(r + 8) * ldc + c] = v1;
        }
    }
}

// ---------------------------------------------------------------------------
// Row softmax, in place. One block of 256 threads per row of 2048 floats.
// ---------------------------------------------------------------------------
__global__ void softmax_kernel(float* __restrict__ attn)
{
    long row = blockIdx.x;
    float* p = attn + row * (long)SKL;
    int t = threadIdx.x;

    float4* p4 = (float4*)p;
    float4 v0 = p4[t];
    float4 v1 = p4[t + 256];

    __shared__ float sh[8];

    float m = fmaxf(fmaxf(fmaxf(v0.x, v0.y), fmaxf(v0.z, v0.w)),
                    fmaxf(fmaxf(v1.x, v1.y), fmaxf(v1.z, v1.w)));
#pragma unroll
    for (int o = 16; o > 0; o >>= 1)
        m = fmaxf(m, __shfl_xor_sync(0xffffffffu, m, o));
    if ((t & 31) == 0) sh[t >> 5] = m;
    __syncthreads();
    {
        float mm = sh[0];
#pragma unroll
        for (int w = 1; w < 8; w++) mm = fmaxf(mm, sh[w]);
        m = mm;
    }
    __syncthreads();

    v0.x = __expf(v0.x - m); v0.y = __expf(v0.y - m);
    v0.z = __expf(v0.z - m); v0.w = __expf(v0.w - m);
    v1.x = __expf(v1.x - m); v1.y = __expf(v1.y - m);
    v1.z = __expf(v1.z - m); v1.w = __expf(v1.w - m);

    float s = v0.x + v0.y + v0.z + v0.w + v1.x + v1.y + v1.z + v1.w;
#pragma unroll
    for (int o = 16; o > 0; o >>= 1)
        s += __shfl_xor_sync(0xffffffffu, s, o);
    if ((t & 31) == 0) sh[t >> 5] = s;
    __syncthreads();
    {
        float ss = sh[0];
#pragma unroll
        for (int w = 1; w < 8; w++) ss += sh[w];
        s = ss;
    }

    float r = 1.0f / s;
    v0.x *= r; v0.y *= r; v0.z *= r; v0.w *= r;
    v1.x *= r; v1.y *= r; v1.z *= r; v1.w *= r;

    p4[t]       = v0;
    p4[t + 256] = v1;
}

// ---------------------------------------------------------------------------
extern "C" void kernel_launch(void* const* d_in, const int* in_sizes, int n_in,
                              void* d_out, int out_size)
{
    const float* query = (const float*)d_in[0];
    const float* key   = (const float*)d_in[1];
    const float* value = (const float*)d_in[2];
    const float* Wq    = (const float*)d_in[3];
    const float* bq    = (const float*)d_in[4];
    const float* Wk    = (const float*)d_in[5];
    const float* bk    = (const float*)d_in[6];
    const float* Wv    = (const float*)d_in[7];
    const float* bv    = (const float*)d_in[8];
    const float* Wo    = (const float*)d_in[9];
    const float* bo    = (const float*)d_in[10];
    float* out = (float*)d_out;

    float *Qp, *Kp, *Vp, *AOp, *attn_fb;
    cudaGetSymbolAddress((void**)&Qp,  g_Q);
    cudaGetSymbolAddress((void**)&Kp,  g_K);
    cudaGetSymbolAddress((void**)&Vp,  g_V);
    cudaGetSymbolAddress((void**)&AOp, g_AO);
    cudaGetSymbolAddress((void**)&attn_fb, g_attn_fb);

    const long OUT_ELEMS  = (long)BATCH * SQL * E_DIM;
    const long ATTN_ELEMS = (long)BATCH * NHEAD * SQL * (long)SKL;
    float* attn = ((long)out_size >= OUT_ELEMS + ATTN_ELEMS) ? (out + OUT_ELEMS)
                                                             : attn_fb;

    // Kernel instantiations
    auto knt = mma_gemm<128, 128, 32, 2, 4, true>;   // NT, 128x128 tiles
    auto knn = mma_gemm<128,  64, 32, 4, 2, false>;  // NN, 128x64 tiles (PV)

    // smem: 2 stages of raw fp32 tiles
    const int SM_NT = (2 * 128 * 36 + 2 * 128 * 36) * 4;   // 73728 B
    const int SM_NN = (2 * 128 * 36 + 2 *  64 * 33) * 4;   // 53760 B
    cudaFuncSetAttribute(knt, cudaFuncAttributeMaxDynamicSharedMemorySize, SM_NT);
    cudaFuncSetAttribute(knn, cudaFuncAttributeMaxDynamicSharedMemorySize, SM_NN);

    dim3 blk(256);

    // 1) QKV projections: [8192,1024] @ W^T + b
    {
        dim3 g(E_DIM / 128, (BATCH * SQL) / 128, 1);
        knt<<<g, blk, SM_NT>>>(query, E_DIM, 0, 0, Wq, E_DIM, 0, 0,
                               Qp, E_DIM, 0, 0, bq, E_DIM, 1.0f, 1);
        knt<<<g, blk, SM_NT>>>(key,   E_DIM, 0, 0, Wk, E_DIM, 0, 0,
                               Kp, E_DIM, 0, 0, bk, E_DIM, 1.0f, 1);
        knt<<<g, blk, SM_NT>>>(value, E_DIM, 0, 0, Wv, E_DIM, 0, 0,
                               Vp, E_DIM, 0, 0, bv, E_DIM, 1.0f, 1);
    }

    // 2) scores = (Q_h @ K_h^T) / 8 per (b,h)
    {
        dim3 g(SKL / 128, SQL / 128, BATCH * NHEAD);
        knt<<<g, blk, SM_NT>>>(
            Qp, E_DIM, (long)SQL * E_DIM, (long)HDIM,
            Kp, E_DIM, (long)SKL * E_DIM, (long)HDIM,
            attn, SKL, (long)NHEAD * SQL * SKL, (long)SQL * SKL,
            nullptr, HDIM, 0.125f, NHEAD);
    }

    // 3) softmax rows, in place
    softmax_kernel<<<BATCH * NHEAD * SQL, 256>>>(attn);

    // 4) attn_out_h = attn @ V_h per (b,h)
    {
        dim3 g(HDIM / 64, SQL / 128, BATCH * NHEAD);
        knn<<<g, blk, SM_NN>>>(
            attn, SKL, (long)NHEAD * SQL * SKL, (long)SQL * SKL,
            Vp, E_DIM, (long)SKL * E_DIM, (long)HDIM,
            AOp, E_DIM, (long)SQL * E_DIM, (long)HDIM,
            nullptr, SKL, 1.0f, NHEAD);
    }

    // 5) output = attn_out @ Wo^T + bo
    {
        dim3 g(E_DIM / 128, (BATCH * SQL) / 128, 1);
        knt<<<g, blk, SM_NT>>>(AOp, E_DIM, 0, 0, Wo, E_DIM, 0, 0,
                               out, E_DIM, 0, 0, bo, E_DIM, 1.0f, 1);
    }
}

// round 12
// speedup vs baseline: 2.1695x; 1.8234x over previous
#include <cuda_runtime.h>
#include <math.h>

// Problem constants
#define E_DIM 1024
#define NHEAD 16
#define HDIM  64
#define BATCH 4
#define SQL   2048
#define SKL   2048

// Scratch (allocation-free rule: __device__ globals)
__device__ float g_Q [BATCH * SQL * E_DIM];
__device__ float g_K [BATCH * SKL * E_DIM];
__device__ float g_V [BATCH * SKL * E_DIM];
__device__ float g_AO[BATCH * SQL * E_DIM];
__device__ float g_attn_fb[268435456];   // fallback if out only covers `output`

// ---------------------------------------------------------------------------
// Mask-based tf32 split: hi = top-10-mantissa part (exactly tf32), lo = x - hi
// (exact in fp32). No cvt instructions; robust to HW operand conversion mode.
// ---------------------------------------------------------------------------
__device__ __forceinline__ void msplit(float x, unsigned& hi, unsigned& lo)
{
    unsigned hb = __float_as_uint(x) & 0xFFFFE000u;
    hi = hb;
    lo = __float_as_uint(x - __uint_as_float(hb));
}

__device__ __forceinline__ void mma_tf32(float* d, const unsigned* a, const unsigned* b)
{
    asm volatile(
        "mma.sync.aligned.m16n8k8.row.col.f32.tf32.tf32.f32 "
        "{%0,%1,%2,%3}, {%4,%5,%6,%7}, {%8,%9}, {%0,%1,%2,%3};"
        : "+f"(d[0]), "+f"(d[1]), "+f"(d[2]), "+f"(d[3])
        : "r"(a[0]), "r"(a[1]), "r"(a[2]), "r"(a[3]), "r"(b[0]), "r"(b[1]));
}

// cp.async helpers
__device__ __forceinline__ void cp_async16(void* dst, const void* src)
{
    unsigned d = (unsigned)__cvta_generic_to_shared(dst);
    asm volatile("cp.async.cg.shared.global [%0], [%1], 16;\n" :: "r"(d), "l"(src));
}
__device__ __forceinline__ void cp_async4(void* dst, const void* src)
{
    unsigned d = (unsigned)__cvta_generic_to_shared(dst);
    asm volatile("cp.async.ca.shared.global [%0], [%1], 4;\n" :: "r"(d), "l"(src));
}
__device__ __forceinline__ void cp_commit() { asm volatile("cp.async.commit_group;\n" ::: "memory"); }
__device__ __forceinline__ void cp_wait1()  { asm volatile("cp.async.wait_group 1;\n" ::: "memory"); }

// ---------------------------------------------------------------------------
// Tensor-core batched GEMM, tf32 3-pass split, 3-stage cp.async ring.
//   NT:  C = alpha*(A @ B^T) + bias   A:[M,K] lda, B:[N,K] ldb
//   NN:  C = alpha*(A @ B)   + bias   A:[M,K] lda, B:[K,N] ldb
// One __syncthreads per k-tile. Raw fp32 in smem; mask-split at fragment load.
// ---------------------------------------------------------------------------
template<int BM, int BN, int BK, int WR, int WC, bool NT>
__global__ void __launch_bounds__(256, 2) mma_gemm(
    const float* __restrict__ A, int lda, long sAb, long sAh,
    const float* __restrict__ B, int ldb, long sBb, long sBh,
    float* __restrict__ C, int ldc, long sCb, long sCh,
    const float* __restrict__ bias, int K, float alpha, int hPer)
{
    constexpr int WM = BM / WR, WN = BN / WC;
    constexpr int MT_M = WM / 16, MT_N = WN / 8;
    constexpr int PA = BK + 4;                 // rows 16B-aligned (36 floats)
    constexpr int PB = NT ? (BK + 4) : (BK + 1);
    constexpr int NTHREADS = WR * WC * 32;
    constexpr int ASZ = BM * PA, BSZ = BN * PB;

    int bz = blockIdx.z;
    int b = bz / hPer, h = bz - b * hPer;
    A += (long)b * sAb + (long)h * sAh;
    B += (long)b * sBb + (long)h * sBh;
    C += (long)b * sCb + (long)h * sCh;

    extern __shared__ float sm[];
    float* As[3] = { sm, sm + (ASZ + BSZ), sm + 2 * (ASZ + BSZ) };
    float* Bs[3] = { sm + ASZ, sm + (ASZ + BSZ) + ASZ, sm + 2 * (ASZ + BSZ) + ASZ };

    const int tid  = threadIdx.x;
    const int warp = tid >> 5, lane = tid & 31;
    const int lr = lane >> 2, lc = lane & 3;
    const int wm = (warp / WC) * WM;
    const int wn = (warp % WC) * WN;
    const int row0 = blockIdx.y * BM, col0 = blockIdx.x * BN;

    float acc[MT_M][MT_N][4];
#pragma unroll
    for (int i = 0; i < MT_M; i++)
#pragma unroll
        for (int j = 0; j < MT_N; j++)
#pragma unroll
            for (int q = 0; q < 4; q++) acc[i][j][q] = 0.0f;

    const int nt = K / BK;

    auto stage = [&](int k0, int buf) {
        float* Ad = As[buf];
        float* Bd = Bs[buf];
#pragma unroll
        for (int i = tid; i < BM * (BK / 4); i += NTHREADS) {
            int r = i / (BK / 4), cq = i % (BK / 4);
            cp_async16(&Ad[r * PA + cq * 4], &A[(long)(row0 + r) * lda + k0 + cq * 4]);
        }
        if (NT) {
#pragma unroll
            for (int i = tid; i < BN * (BK / 4); i += NTHREADS) {
                int r = i / (BK / 4), cq = i % (BK / 4);
                cp_async16(&Bd[r * PB + cq * 4], &B[(long)(col0 + r) * ldb + k0 + cq * 4]);
            }
        } else {
#pragma unroll
            for (int i = tid; i < BK * BN; i += NTHREADS) {
                int kr = i / BN, n = i % BN;
                cp_async4(&Bd[n * PB + kr], &B[(long)(k0 + kr) * ldb + col0 + n]);
            }
        }
    };

    stage(0, 0);
    cp_commit();
    if (nt > 1) { stage(BK, 1); }
    cp_commit();

    for (int t = 0; t < nt; t++) {
        cp_wait1();          // stage t complete (≤1 group = the in-flight t+1)
        __syncthreads();     // all threads see buffer t; prior compute on (t+2)%3 done

        if (t + 2 < nt) stage((t + 2) * BK, (t + 2) % 3);
        cp_commit();         // commit (possibly empty) keeps group accounting uniform

        const float* Ab = As[t % 3];
        const float* Bb = Bs[t % 3];

#pragma unroll
        for (int kk = 0; kk < BK; kk += 8) {
            unsigned bh[MT_N][2], bl[MT_N][2];
#pragma unroll
            for (int in = 0; in < MT_N; in++) {
                int n = wn + in * 8 + lr;
                msplit(Bb[n * PB + kk + lc],     bh[in][0], bl[in][0]);
                msplit(Bb[n * PB + kk + lc + 4], bh[in][1], bl[in][1]);
            }
#pragma unroll
            for (int im = 0; im < MT_M; im++) {
                int r = wm + im * 16 + lr;
                unsigned ah[4], al[4];
                msplit(Ab[r * PA + kk + lc],           ah[0], al[0]);
                msplit(Ab[(r + 8) * PA + kk + lc],     ah[1], al[1]);
                msplit(Ab[r * PA + kk + lc + 4],       ah[2], al[2]);
                msplit(Ab[(r + 8) * PA + kk + lc + 4], ah[3], al[3]);
#pragma unroll
                for (int in = 0; in < MT_N; in++) {
                    mma_tf32(acc[im][in], ah, bh[in]);   // hi*hi
                    mma_tf32(acc[im][in], ah, bl[in]);   // hi*lo
                    mma_tf32(acc[im][in], al, bh[in]);   // lo*hi
                }
            }
        }
    }

    // ---- epilogue ----
#pragma unroll
    for (int im = 0; im < MT_M; im++) {
#pragma unroll
        for (int in = 0; in < MT_N; in++) {
            int r = row0 + wm + im * 16 + lr;
            int c = col0 + wn + in * 8 + lc * 2;
            float b0 = bias ? bias[c]     : 0.0f;
            float b1 = bias ? bias[c + 1] : 0.0f;
            float2 v0 = { acc[im][in][0] * alpha + b0, acc[im][in][1] * alpha + b1 };
            float2 v1 = { acc[im][in][2] * alpha + b0, acc[im][in][3] * alpha + b1 };
            *(float2*)&C[(long)r * ldc + c]       = v0;
            *(float2*)&C[(long)(r + 8) * ldc + c] = v1;
        }
    }
}

// ---------------------------------------------------------------------------
// Row softmax, in place. One block of 256 threads per row of 2048 floats.
// ---------------------------------------------------------------------------
__global__ void softmax_kernel(float* __restrict__ attn)
{
    long row = blockIdx.x;
    float* p = attn + row * (long)SKL;
    int t = threadIdx.x;

    float4* p4 = (float4*)p;
    float4 v0 = p4[t];
    float4 v1 = p4[t + 256];

    __shared__ float sh[8];

    float m = fmaxf(fmaxf(fmaxf(v0.x, v0.y), fmaxf(v0.z, v0.w)),
                    fmaxf(fmaxf(v1.x, v1.y), fmaxf(v1.z, v1.w)));
#pragma unroll
    for (int o = 16; o > 0; o >>= 1)
        m = fmaxf(m, __shfl_xor_sync(0xffffffffu, m, o));
    if ((t & 31) == 0) sh[t >> 5] = m;
    __syncthreads();
    {
        float mm = sh[0];
#pragma unroll
        for (int w = 1; w < 8; w++) mm = fmaxf(mm, sh[w]);
        m = mm;
    }
    __syncthreads();

    v0.x = __expf(v0.x - m); v0.y = __expf(v0.y - m);
    v0.z = __expf(v0.z - m); v0.w = __expf(v0.w - m);
    v1.x = __expf(v1.x - m); v1.y = __expf(v1.y - m);
    v1.z = __expf(v1.z - m); v1.w = __expf(v1.w - m);

    float s = v0.x + v0.y + v0.z + v0.w + v1.x + v1.y + v1.z + v1.w;
#pragma unroll
    for (int o = 16; o > 0; o >>= 1)
        s += __shfl_xor_sync(0xffffffffu, s, o);
    if ((t & 31) == 0) sh[t >> 5] = s;
    __syncthreads();
    {
        float ss = sh[0];
#pragma unroll
        for (int w = 1; w < 8; w++) ss += sh[w];
        s = ss;
    }

    float r = 1.0f / s;
    v0.x *= r; v0.y *= r; v0.z *= r; v0.w *= r;
    v1.x *= r; v1.y *= r; v1.z *= r; v1.w *= r;

    p4[t]       = v0;
    p4[t + 256] = v1;
}

// ---------------------------------------------------------------------------
extern "C" void kernel_launch(void* const* d_in, const int* in_sizes, int n_in,
                              void* d_out, int out_size)
{
    const float* query = (const float*)d_in[0];
    const float* key   = (const float*)d_in[1];
    const float* value = (const float*)d_in[2];
    const float* Wq    = (const float*)d_in[3];
    const float* bq    = (const float*)d_in[4];
    const float* Wk    = (const float*)d_in[5];
    const float* bk    = (const float*)d_in[6];
    const float* Wv    = (const float*)d_in[7];
    const float* bv    = (const float*)d_in[8];
    const float* Wo    = (const float*)d_in[9];
    const float* bo    = (const float*)d_in[10];
    float* out = (float*)d_out;

    float *Qp, *Kp, *Vp, *AOp, *attn_fb;
    cudaGetSymbolAddress((void**)&Qp,  g_Q);
    cudaGetSymbolAddress((void**)&Kp,  g_K);
    cudaGetSymbolAddress((void**)&Vp,  g_V);
    cudaGetSymbolAddress((void**)&AOp, g_AO);
    cudaGetSymbolAddress((void**)&attn_fb, g_attn_fb);

    const long OUT_ELEMS  = (long)BATCH * SQL * E_DIM;
    const long ATTN_ELEMS = (long)BATCH * NHEAD * SQL * (long)SKL;
    float* attn = ((long)out_size >= OUT_ELEMS + ATTN_ELEMS) ? (out + OUT_ELEMS)
                                                             : attn_fb;

    // Kernel instantiations
    auto knt = mma_gemm<128, 128, 32, 2, 4, true>;   // NT, 128x128 tiles
    auto knn = mma_gemm<128,  64, 32, 4, 2, false>;  // NN, 128x64 tiles (PV)

    // smem: 3 stages of raw fp32 tiles
    const int SM_NT = 3 * (128 * 36 + 128 * 36) * 4;   // 110592 B
    const int SM_NN = 3 * (128 * 36 +  64 * 33) * 4;   //  80640 B
    cudaFuncSetAttribute(knt, cudaFuncAttributeMaxDynamicSharedMemorySize, SM_NT);
    cudaFuncSetAttribute(knn, cudaFuncAttributeMaxDynamicSharedMemorySize, SM_NN);

    dim3 blk(256);

    // 1) QKV projections: [8192,1024] @ W^T + b
    {
        dim3 g(E_DIM / 128, (BATCH * SQL) / 128, 1);
        knt<<<g, blk, SM_NT>>>(query, E_DIM, 0, 0, Wq, E_DIM, 0, 0,
                               Qp, E_DIM, 0, 0, bq, E_DIM, 1.0f, 1);
        knt<<<g, blk, SM_NT>>>(key,   E_DIM, 0, 0, Wk, E_DIM, 0, 0,
                               Kp, E_DIM, 0, 0, bk, E_DIM, 1.0f, 1);
        knt<<<g, blk, SM_NT>>>(value, E_DIM, 0, 0, Wv, E_DIM, 0, 0,
                               Vp, E_DIM, 0, 0, bv, E_DIM, 1.0f, 1);
    }

    // 2) scores = (Q_h @ K_h^T) / 8 per (b,h)
    {
        dim3 g(SKL / 128, SQL / 128, BATCH * NHEAD);
        knt<<<g, blk, SM_NT>>>(
            Qp, E_DIM, (long)SQL * E_DIM, (long)HDIM,
            Kp, E_DIM, (long)SKL * E_DIM, (long)HDIM,
            attn, SKL, (long)NHEAD * SQL * SKL, (long)SQL * SKL,
            nullptr, HDIM, 0.125f, NHEAD);
    }

    // 3) softmax rows, in place
    softmax_kernel<<<BATCH * NHEAD * SQL, 256>>>(attn);

    // 4) attn_out_h = attn @ V_h per (b,h)
    {
        dim3 g(HDIM / 64, SQL / 128, BATCH * NHEAD);
        knn<<<g, blk, SM_NN>>>(
            attn, SKL, (long)NHEAD * SQL * SKL, (long)SQL * SKL,
            Vp, E_DIM, (long)SKL * E_DIM, (long)HDIM,
            AOp, E_DIM, (long)SQL * E_DIM, (long)HDIM,
            nullptr, SKL, 1.0f, NHEAD);
    }

    // 5) output = attn_out @ Wo^T + bo
    {
        dim3 g(E_DIM / 128, (BATCH * SQL) / 128, 1);
        knt<<<g, blk, SM_NT>>>(AOp, E_DIM, 0, 0, Wo, E_DIM, 0, 0,
                               out, E_DIM, 0, 0, bo, E_DIM, 1.0f, 1);
    }
}

// round 13
// speedup vs baseline: 2.8716x; 1.3236x over previous
#include <cuda_runtime.h>
#include <cuda_bf16.h>
#include <math.h>

// Problem constants
#define E_DIM 1024
#define NHEAD 16
#define HDIM  64
#define BATCH 4
#define SQL   2048
#define SKL   2048

#define NQ (BATCH * SQL * E_DIM)    // 8,388,608 elems
#define NW (E_DIM * E_DIM)          // 1,048,576 elems

// ---------------- scratch (allocation-free rule: __device__ globals) -------
// bf16 hi/lo planes of inputs + weights
__device__ __nv_bfloat16 g_qh[NQ], g_ql[NQ], g_kh[NQ], g_kl[NQ], g_vh[NQ], g_vl[NQ];
__device__ __nv_bfloat16 g_wqh[NW], g_wql[NW], g_wkh[NW], g_wkl[NW];
__device__ __nv_bfloat16 g_wvh[NW], g_wvl[NW], g_woh[NW], g_wol[NW];
// bf16 hi/lo planes of intermediates
__device__ __nv_bfloat16 gQh[NQ], gQl[NQ], gKh[NQ], gKl[NQ];
__device__ __nv_bfloat16 gVth[NQ], gVtl[NQ];       // V transposed: [b][e][s]
__device__ __nv_bfloat16 gAOh[NQ], gAOl[NQ];
__device__ __nv_bfloat16 gPh[268435456], gPl[268435456];
// fallback attn buffer if out only covers `output`
__device__ float g_attn_fb[268435456];

// ---------------------------------------------------------------------------
__device__ __forceinline__ void mma_bf16(float* d, const unsigned* a, const unsigned* b)
{
    asm volatile(
        "mma.sync.aligned.m16n8k16.row.col.f32.bf16.bf16.f32 "
        "{%0,%1,%2,%3}, {%4,%5,%6,%7}, {%8,%9}, {%0,%1,%2,%3};"
        : "+f"(d[0]), "+f"(d[1]), "+f"(d[2]), "+f"(d[3])
        : "r"(a[0]), "r"(a[1]), "r"(a[2]), "r"(a[3]), "r"(b[0]), "r"(b[1]));
}

__device__ __forceinline__ void cp_async16(void* dst, const void* src)
{
    unsigned d = (unsigned)__cvta_generic_to_shared(dst);
    asm volatile("cp.async.cg.shared.global [%0], [%1], 16;\n" :: "r"(d), "l"(src));
}
__device__ __forceinline__ void cp_commit() { asm volatile("cp.async.commit_group;\n" ::: "memory"); }
__device__ __forceinline__ void cp_wait1()  { asm volatile("cp.async.wait_group 1;\n" ::: "memory"); }

__device__ __forceinline__ void bf_split(float v, __nv_bfloat16& h, __nv_bfloat16& l)
{
    h = __float2bfloat16(v);
    l = __float2bfloat16(v - __bfloat162float(h));
}

// ---------------------------------------------------------------------------
// Convert fp32 -> bf16 hi/lo planes
// ---------------------------------------------------------------------------
__global__ void cvt_planes(const float4* __restrict__ src,
                           __nv_bfloat162* __restrict__ dh,
                           __nv_bfloat162* __restrict__ dl, int n4)
{
    int i = blockIdx.x * blockDim.x + threadIdx.x;
    if (i >= n4) return;
    float4 v = src[i];
    __nv_bfloat16 hx, lx, hy, ly, hz, lz, hw, lw;
    bf_split(v.x, hx, lx); bf_split(v.y, hy, ly);
    bf_split(v.z, hz, lz); bf_split(v.w, hw, lw);
    __nv_bfloat162 a; a.x = hx; a.y = hy;
    __nv_bfloat162 b; b.x = hz; b.y = hw;
    dh[2 * i] = a; dh[2 * i + 1] = b;
    a.x = lx; a.y = ly; b.x = lz; b.y = lw;
    dl[2 * i] = a; dl[2 * i + 1] = b;
}

// ---------------------------------------------------------------------------
// NT GEMM on bf16 hi/lo planes: C = alpha*(A @ B^T) + bias
//   A planes: [M,K] row-major (lda), B planes: [N,K] row-major (ldb)
// EPI: 0 = fp32 C, 1 = bf16 hi/lo plane C, 2 = transposed plane C (V only)
// smem row: 36 words = 16 hi-words (32 bf16) + 16 lo-words + 4 pad.
// 3-stage cp.async ring, one __syncthreads per k-tile (BK=32).
// ---------------------------------------------------------------------------
template<int BM, int BN, int BK, int WR, int WC, int EPI>
__global__ void __launch_bounds__(256, 2) bf_gemm(
    const __nv_bfloat16* __restrict__ Ah, const __nv_bfloat16* __restrict__ Al,
    int lda, long sAb, long sAh,
    const __nv_bfloat16* __restrict__ Bh, const __nv_bfloat16* __restrict__ Bl,
    int ldb, long sBb, long sBh,
    float* __restrict__ Cf, __nv_bfloat16* __restrict__ Ch, __nv_bfloat16* __restrict__ Cl,
    int ldc, long sCb, long sCh,
    const float* __restrict__ bias, int K, float alpha, int hPer)
{
    static_assert(BK == 32, "row layout assumes BK=32");
    constexpr int WM = BM / WR, WN = BN / WC;
    constexpr int MT_M = WM / 16, MT_N = WN / 8;
    constexpr int PW = 36;                       // words per smem row
    constexpr int ASZ = BM * PW, BSZ = BN * PW;  // words
    constexpr int STG = ASZ + BSZ;

    int bz = blockIdx.z;
    int b = bz / hPer, h = bz - b * hPer;
    Ah += (long)b * sAb + (long)h * sAh;  Al += (long)b * sAb + (long)h * sAh;
    Bh += (long)b * sBb + (long)h * sBh;  Bl += (long)b * sBb + (long)h * sBh;
    long coff = (long)b * sCb + (long)h * sCh;

    extern __shared__ unsigned smw[];

    const int tid  = threadIdx.x;
    const int warp = tid >> 5, lane = tid & 31;
    const int lr = lane >> 2, lc = lane & 3;
    const int wm = (warp / WC) * WM;
    const int wn = (warp % WC) * WN;
    const int row0 = blockIdx.y * BM, col0 = blockIdx.x * BN;

    float acc[MT_M][MT_N][4];
#pragma unroll
    for (int i = 0; i < MT_M; i++)
#pragma unroll
        for (int j = 0; j < MT_N; j++)
#pragma unroll
            for (int q = 0; q < 4; q++) acc[i][j][q] = 0.0f;

    const int nt = K / BK;

    auto stage = [&](int k0, int buf) {
        unsigned* SA = smw + buf * STG;
        unsigned* SB = SA + ASZ;
#pragma unroll 2
        for (int i = tid; i < BM * 4; i += 256) {
            int r = i >> 2, ch = i & 3;
            long go = (long)(row0 + r) * lda + k0 + ch * 8;
            cp_async16(&SA[r * PW + ch * 4],      Ah + go);
            cp_async16(&SA[r * PW + 16 + ch * 4], Al + go);
        }
#pragma unroll 2
        for (int i = tid; i < BN * 4; i += 256) {
            int r = i >> 2, ch = i & 3;
            long go = (long)(col0 + r) * ldb + k0 + ch * 8;
            cp_async16(&SB[r * PW + ch * 4],      Bh + go);
            cp_async16(&SB[r * PW + 16 + ch * 4], Bl + go);
        }
    };

    stage(0, 0);
    cp_commit();
    if (nt > 1) stage(BK, 1);
    cp_commit();

    for (int t = 0; t < nt; t++) {
        cp_wait1();
        __syncthreads();

        if (t + 2 < nt) stage((t + 2) * BK, (t + 2) % 3);
        cp_commit();

        const unsigned* SA = smw + (t % 3) * STG;
        const unsigned* SB = SA + ASZ;

#pragma unroll
        for (int kk = 0; kk < 2; kk++) {         // two k16 steps per tile
            const int wb = kk * 8;
            unsigned bh_[MT_N][2], bl_[MT_N][2];
#pragma unroll
            for (int in = 0; in < MT_N; in++) {
                int n = wn + in * 8 + lr;
                bh_[in][0] = SB[n * PW + wb + lc];
                bh_[in][1] = SB[n * PW + wb + 4 + lc];
                bl_[in][0] = SB[n * PW + 16 + wb + lc];
                bl_[in][1] = SB[n * PW + 16 + wb + 4 + lc];
            }
#pragma unroll
            for (int im = 0; im < MT_M; im++) {
                int r = wm + im * 16 + lr;
                unsigned ah_[4], al_[4];
                ah_[0] = SA[r * PW + wb + lc];
                ah_[1] = SA[(r + 8) * PW + wb + lc];
                ah_[2] = SA[r * PW + wb + 4 + lc];
                ah_[3] = SA[(r + 8) * PW + wb + 4 + lc];
                al_[0] = SA[r * PW + 16 + wb + lc];
                al_[1] = SA[(r + 8) * PW + 16 + wb + lc];
                al_[2] = SA[r * PW + 16 + wb + 4 + lc];
                al_[3] = SA[(r + 8) * PW + 16 + wb + 4 + lc];
#pragma unroll
                for (int in = 0; in < MT_N; in++) {
                    mma_bf16(acc[im][in], ah_, bh_[in]);   // hi*hi
                    mma_bf16(acc[im][in], ah_, bl_[in]);   // hi*lo
                    mma_bf16(acc[im][in], al_, bh_[in]);   // lo*hi
                }
            }
        }
    }

    // ---- epilogue ----
#pragma unroll
    for (int im = 0; im < MT_M; im++) {
#pragma unroll
        for (int in = 0; in < MT_N; in++) {
            int r = row0 + wm + im * 16 + lr;
            int c = col0 + wn + in * 8 + lc * 2;
            float v00 = acc[im][in][0] * alpha, v01 = acc[im][in][1] * alpha;
            float v10 = acc[im][in][2] * alpha, v11 = acc[im][in][3] * alpha;
            if (bias) {
                float b0 = bias[c], b1 = bias[c + 1];
                v00 += b0; v01 += b1; v10 += b0; v11 += b1;
            }
            if (EPI == 0) {
                float2 a = { v00, v01 }, bq = { v10, v11 };
                *(float2*)&Cf[coff + (long)r * ldc + c]       = a;
                *(float2*)&Cf[coff + (long)(r + 8) * ldc + c] = bq;
            } else if (EPI == 1) {
                __nv_bfloat16 h00, l00, h01, l01, h10, l10, h11, l11;
                bf_split(v00, h00, l00); bf_split(v01, h01, l01);
                bf_split(v10, h10, l10); bf_split(v11, h11, l11);
                __nv_bfloat162 t2;
                t2.x = h00; t2.y = h01; *(__nv_bfloat162*)&Ch[coff + (long)r * ldc + c] = t2;
                t2.x = l00; t2.y = l01; *(__nv_bfloat162*)&Cl[coff + (long)r * ldc + c] = t2;
                t2.x = h10; t2.y = h11; *(__nv_bfloat162*)&Ch[coff + (long)(r + 8) * ldc + c] = t2;
                t2.x = l10; t2.y = l11; *(__nv_bfloat162*)&Cl[coff + (long)(r + 8) * ldc + c] = t2;
            } else {
                // transposed planes for V: dst[b][e=c][s=r%SKL]
                int bb = r >> 11, ss = r & (SKL - 1);
                long base = (long)bb * E_DIM * SKL + ss;
                __nv_bfloat16 h00, l00, h01, l01, h10, l10, h11, l11;
                bf_split(v00, h00, l00); bf_split(v01, h01, l01);
                bf_split(v10, h10, l10); bf_split(v11, h11, l11);
                Ch[base + (long)c * SKL]           = h00;
                Ch[base + (long)(c + 1) * SKL]     = h01;
                Ch[base + (long)c * SKL + 8]       = h10;
                Ch[base + (long)(c + 1) * SKL + 8] = h11;
                Cl[base + (long)c * SKL]           = l00;
                Cl[base + (long)(c + 1) * SKL]     = l01;
                Cl[base + (long)c * SKL + 8]       = l10;
                Cl[base + (long)(c + 1) * SKL + 8] = l11;
            }
        }
    }
}

// ---------------------------------------------------------------------------
// Row softmax, in place; also emits bf16 hi/lo planes of the result (for PV).
// ---------------------------------------------------------------------------
__global__ void softmax_kernel(float* __restrict__ attn,
                               __nv_bfloat16* __restrict__ ph,
                               __nv_bfloat16* __restrict__ pl)
{
    long row = blockIdx.x;
    float* p = attn + row * (long)SKL;
    int t = threadIdx.x;

    float4* p4 = (float4*)p;
    float4 v0 = p4[t];
    float4 v1 = p4[t + 256];

    __shared__ float sh[8];

    float m = fmaxf(fmaxf(fmaxf(v0.x, v0.y), fmaxf(v0.z, v0.w)),
                    fmaxf(fmaxf(v1.x, v1.y), fmaxf(v1.z, v1.w)));
#pragma unroll
    for (int o = 16; o > 0; o >>= 1)
        m = fmaxf(m, __shfl_xor_sync(0xffffffffu, m, o));
    if ((t & 31) == 0) sh[t >> 5] = m;
    __syncthreads();
    {
        float mm = sh[0];
#pragma unroll
        for (int w = 1; w < 8; w++) mm = fmaxf(mm, sh[w]);
        m = mm;
    }
    __syncthreads();

    v0.x = __expf(v0.x - m); v0.y = __expf(v0.y - m);
    v0.z = __expf(v0.z - m); v0.w = __expf(v0.w - m);
    v1.x = __expf(v1.x - m); v1.y = __expf(v1.y - m);
    v1.z = __expf(v1.z - m); v1.w = __expf(v1.w - m);

    float s = v0.x + v0.y + v0.z + v0.w + v1.x + v1.y + v1.z + v1.w;
#pragma unroll
    for (int o = 16; o > 0; o >>= 1)
        s += __shfl_xor_sync(0xffffffffu, s, o);
    if ((t & 31) == 0) sh[t >> 5] = s;
    __syncthreads();
    {
        float ss = sh[0];
#pragma unroll
        for (int w = 1; w < 8; w++) ss += sh[w];
        s = ss;
    }

    float r = 1.0f / s;
    v0.x *= r; v0.y *= r; v0.z *= r; v0.w *= r;
    v1.x *= r; v1.y *= r; v1.z *= r; v1.w *= r;

    p4[t]       = v0;
    p4[t + 256] = v1;

    // bf16 hi/lo planes
    long o0 = row * (long)SKL + 4 * t;
    long o1 = o0 + 1024;
    __nv_bfloat16 h, l;
    __nv_bfloat162 t2;
#define EMIT(VV, OFF)                                                          \
    {                                                                          \
        __nv_bfloat16 ha, la, hb, lb;                                          \
        bf_split(VV.x, ha, la); bf_split(VV.y, hb, lb);                        \
        t2.x = ha; t2.y = hb; *(__nv_bfloat162*)&ph[OFF] = t2;                 \
        t2.x = la; t2.y = lb; *(__nv_bfloat162*)&pl[OFF] = t2;                 \
        bf_split(VV.z, ha, la); bf_split(VV.w, hb, lb);                        \
        t2.x = ha; t2.y = hb; *(__nv_bfloat162*)&ph[OFF + 2] = t2;             \
        t2.x = la; t2.y = lb; *(__nv_bfloat162*)&pl[OFF + 2] = t2;             \
    }
    EMIT(v0, o0);
    EMIT(v1, o1);
#undef EMIT
    (void)h; (void)l;
}

// ---------------------------------------------------------------------------
extern "C" void kernel_launch(void* const* d_in, const int* in_sizes, int n_in,
                              void* d_out, int out_size)
{
    const float* query = (const float*)d_in[0];
    const float* key   = (const float*)d_in[1];
    const float* value = (const float*)d_in[2];
    const float* Wq    = (const float*)d_in[3];
    const float* bq    = (const float*)d_in[4];
    const float* Wk    = (const float*)d_in[5];
    const float* bk    = (const float*)d_in[6];
    const float* Wv    = (const float*)d_in[7];
    const float* bv    = (const float*)d_in[8];
    const float* Wo    = (const float*)d_in[9];
    const float* bo    = (const float*)d_in[10];
    float* out = (float*)d_out;

    // symbol addresses
    __nv_bfloat16 *qh, *ql, *kh, *kl, *vh, *vl;
    __nv_bfloat16 *wqh, *wql, *wkh, *wkl, *wvh, *wvl, *woh, *wol;
    __nv_bfloat16 *Qh, *Ql, *Kh, *Kl, *Vth, *Vtl, *AOh, *AOl, *Ph, *Pl;
    float* attn_fb;
    cudaGetSymbolAddress((void**)&qh, g_qh);   cudaGetSymbolAddress((void**)&ql, g_ql);
    cudaGetSymbolAddress((void**)&kh, g_kh);   cudaGetSymbolAddress((void**)&kl, g_kl);
    cudaGetSymbolAddress((void**)&vh, g_vh);   cudaGetSymbolAddress((void**)&vl, g_vl);
    cudaGetSymbolAddress((void**)&wqh, g_wqh); cudaGetSymbolAddress((void**)&wql, g_wql);
    cudaGetSymbolAddress((void**)&wkh, g_wkh); cudaGetSymbolAddress((void**)&wkl, g_wkl);
    cudaGetSymbolAddress((void**)&wvh, g_wvh); cudaGetSymbolAddress((void**)&wvl, g_wvl);
    cudaGetSymbolAddress((void**)&woh, g_woh); cudaGetSymbolAddress((void**)&wol, g_wol);
    cudaGetSymbolAddress((void**)&Qh, gQh);    cudaGetSymbolAddress((void**)&Ql, gQl);
    cudaGetSymbolAddress((void**)&Kh, gKh);    cudaGetSymbolAddress((void**)&Kl, gKl);
    cudaGetSymbolAddress((void**)&Vth, gVth);  cudaGetSymbolAddress((void**)&Vtl, gVtl);
    cudaGetSymbolAddress((void**)&AOh, gAOh);  cudaGetSymbolAddress((void**)&AOl, gAOl);
    cudaGetSymbolAddress((void**)&Ph, gPh);    cudaGetSymbolAddress((void**)&Pl, gPl);
    cudaGetSymbolAddress((void**)&attn_fb, g_attn_fb);

    const long OUT_ELEMS  = (long)BATCH * SQL * E_DIM;
    const long ATTN_ELEMS = (long)BATCH * NHEAD * SQL * (long)SKL;
    float* attn = ((long)out_size >= OUT_ELEMS + ATTN_ELEMS) ? (out + OUT_ELEMS)
                                                             : attn_fb;

    // 0) convert inputs + weights to bf16 hi/lo planes
    {
        int n4 = NQ / 4, g = (n4 + 255) / 256;
        cvt_planes<<<g, 256>>>((const float4*)query, (__nv_bfloat162*)qh, (__nv_bfloat162*)ql, n4);
        cvt_planes<<<g, 256>>>((const float4*)key,   (__nv_bfloat162*)kh, (__nv_bfloat162*)kl, n4);
        cvt_planes<<<g, 256>>>((const float4*)value, (__nv_bfloat162*)vh, (__nv_bfloat162*)vl, n4);
        int w4 = NW / 4, gw = (w4 + 255) / 256;
        cvt_planes<<<gw, 256>>>((const float4*)Wq, (__nv_bfloat162*)wqh, (__nv_bfloat162*)wql, w4);
        cvt_planes<<<gw, 256>>>((const float4*)Wk, (__nv_bfloat162*)wkh, (__nv_bfloat162*)wkl, w4);
        cvt_planes<<<gw, 256>>>((const float4*)Wv, (__nv_bfloat162*)wvh, (__nv_bfloat162*)wvl, w4);
        cvt_planes<<<gw, 256>>>((const float4*)Wo, (__nv_bfloat162*)woh, (__nv_bfloat162*)wol, w4);
    }

    auto kplanes = bf_gemm<128, 128, 32, 2, 4, 1>;  // proj -> planes
    auto kplanesT = bf_gemm<128, 128, 32, 2, 4, 2>; // V proj -> transposed planes
    auto kf32    = bf_gemm<128, 128, 32, 2, 4, 0>;  // scores / out-proj -> fp32
    auto kpv     = bf_gemm<128,  64, 32, 4, 2, 1>;  // PV -> AO planes

    const int SM_BIG = 3 * (128 + 128) * 36 * 4;    // 110592 B
    const int SM_PV  = 3 * (128 +  64) * 36 * 4;    //  82944 B
    cudaFuncSetAttribute(kplanes,  cudaFuncAttributeMaxDynamicSharedMemorySize, SM_BIG);
    cudaFuncSetAttribute(kplanesT, cudaFuncAttributeMaxDynamicSharedMemorySize, SM_BIG);
    cudaFuncSetAttribute(kf32,     cudaFuncAttributeMaxDynamicSharedMemorySize, SM_BIG);
    cudaFuncSetAttribute(kpv,      cudaFuncAttributeMaxDynamicSharedMemorySize, SM_PV);

    dim3 blk(256);

    // 1) projections: [8192,1024] @ W^T + b -> planes
    {
        dim3 g(E_DIM / 128, (BATCH * SQL) / 128, 1);
        kplanes<<<g, blk, SM_BIG>>>(qh, ql, E_DIM, 0, 0, wqh, wql, E_DIM, 0, 0,
                                    nullptr, Qh, Ql, E_DIM, 0, 0, bq, E_DIM, 1.0f, 1);
        kplanes<<<g, blk, SM_BIG>>>(kh, kl, E_DIM, 0, 0, wkh, wkl, E_DIM, 0, 0,
                                    nullptr, Kh, Kl, E_DIM, 0, 0, bk, E_DIM, 1.0f, 1);
        kplanesT<<<g, blk, SM_BIG>>>(vh, vl, E_DIM, 0, 0, wvh, wvl, E_DIM, 0, 0,
                                     nullptr, Vth, Vtl, E_DIM, 0, 0, bv, E_DIM, 1.0f, 1);
    }

    // 2) scores = (Q_h @ K_h^T) / 8 per (b,h) -> attn (fp32)
    {
        dim3 g(SKL / 128, SQL / 128, BATCH * NHEAD);
        kf32<<<g, blk, SM_BIG>>>(
            Qh, Ql, E_DIM, (long)SQL * E_DIM, (long)HDIM,
            Kh, Kl, E_DIM, (long)SKL * E_DIM, (long)HDIM,
            attn, nullptr, nullptr, SKL, (long)NHEAD * SQL * SKL, (long)SQL * SKL,
            nullptr, HDIM, 0.125f, NHEAD);
    }

    // 3) softmax rows, in place; emit P planes
    softmax_kernel<<<BATCH * NHEAD * SQL, 256>>>(attn, Ph, Pl);

    // 4) attn_out_h = P @ V_h per (b,h) -> AO planes  (NT with V^T planes)
    {
        dim3 g(1, SQL / 128, BATCH * NHEAD);
        kpv<<<g, blk, SM_PV>>>(
            Ph, Pl, SKL, (long)NHEAD * SQL * SKL, (long)SQL * SKL,
            Vth, Vtl, SKL, (long)E_DIM * SKL, (long)HDIM * SKL,
            nullptr, AOh, AOl, E_DIM, (long)SQL * E_DIM, (long)HDIM,
            nullptr, SKL, 1.0f, NHEAD);
    }

    // 5) output = AO @ Wo^T + bo -> fp32 out
    {
        dim3 g(E_DIM / 128, (BATCH * SQL) / 128, 1);
        kf32<<<g, blk, SM_BIG>>>(AOh, AOl, E_DIM, 0, 0, woh, wol, E_DIM, 0, 0,
                                 out, nullptr, nullptr, E_DIM, 0, 0, bo, E_DIM, 1.0f, 1);
    }
}